// round 2
// baseline (speedup 1.0000x reference)
#include <cuda_runtime.h>
#include <math.h>

#define CC 256
#define HH 4
#define NMAX 500000
#define PMAX 50000
#define TILE_P 32

// ---------------- device scratch (no allocations allowed) ----------------
__device__ float    g_Q[CC];
__device__ float    g_qw[HH * CC];
__device__ float    g_qc[HH];
__device__ float    g_WvT[CC * CC];
__device__ float    g_WoT[CC * CC];
__device__ float    g_scoreE[(size_t)NMAX * HH];   // scores, then exp(score-max) in place
__device__ unsigned g_smax[PMAX * HH];
__device__ float    g_denom[PMAX * HH];
__device__ int      g_count[PMAX];
__device__ int      g_offsets[PMAX + 1];
__device__ int      g_fill[PMAX];
__device__ int      g_order[NMAX];
__device__ float    g_xbar[(size_t)PMAX * HH * CC];  // 204.8 MB

// ---------------- helpers ----------------
__device__ __forceinline__ unsigned encf(float f) {
    unsigned u = __float_as_uint(f);
    return (u & 0x80000000u) ? ~u : (u | 0x80000000u);
}
__device__ __forceinline__ float decf(unsigned u) {
    return (u & 0x80000000u) ? __uint_as_float(u ^ 0x80000000u) : __uint_as_float(~u);
}
__device__ __forceinline__ unsigned long long pk2(float x, float y) {
    unsigned long long r;
    asm("mov.b64 %0, {%1,%2};" : "=l"(r) : "f"(x), "f"(y));
    return r;
}
__device__ __forceinline__ float hadd2(unsigned long long v) {
    float x, y;
    asm("mov.b64 {%0,%1}, %2;" : "=f"(x), "=f"(y) : "l"(v));
    return x + y;
}
__device__ __forceinline__ void fma2(unsigned long long& d, unsigned long long a, unsigned long long b) {
    asm("fma.rn.f32x2 %0, %1, %2, %0;" : "+l"(d) : "l"(a), "l"(b));
}

// ---------------- kernels ----------------
__global__ void k_init(int P) {
    int i = blockIdx.x * blockDim.x + threadIdx.x;
    int st = gridDim.x * blockDim.x;
    for (int j = i; j < P * HH; j += st) { g_smax[j] = 0u; g_denom[j] = 0.f; }
    for (int j = i; j < P; j += st)      { g_count[j] = 0;  g_fill[j] = 0; }
}

// Q = S @ Wq^T + bq
__global__ void k_q(const float* __restrict__ S, const float* __restrict__ Wq,
                    const float* __restrict__ bq) {
    __shared__ float sS[CC];
    int c = threadIdx.x;
    sS[c] = S[c];
    __syncthreads();
    const float4* wr = (const float4*)(Wq + (size_t)c * CC);
    float acc = 0.f;
    #pragma unroll 8
    for (int j = 0; j < CC / 4; j++) {
        float4 w = wr[j];
        acc += sS[4*j] * w.x + sS[4*j+1] * w.y + sS[4*j+2] * w.z + sS[4*j+3] * w.w;
    }
    g_Q[c] = acc + bq[c];
}

// qw[h][j] = (1/16) sum_{cc<64} Q[64h+cc] * Wk[64h+cc][j];  qc[h] = (1/16) sum Q*bk
__global__ void k_qw(const float* __restrict__ Wk, const float* __restrict__ bk) {
    int h = blockIdx.x;
    int j = threadIdx.x;
    __shared__ float sQ[64];
    if (j < 64) sQ[j] = g_Q[h * 64 + j];
    __syncthreads();
    float acc = 0.f;
    #pragma unroll 8
    for (int cc = 0; cc < 64; cc++)
        acc += sQ[cc] * Wk[(size_t)(h * 64 + cc) * CC + j];
    g_qw[h * CC + j] = acc * 0.0625f;
    if (j == 0) {
        float q = 0.f;
        for (int cc = 0; cc < 64; cc++) q += sQ[cc] * bk[h * 64 + cc];
        g_qc[h] = q * 0.0625f;
    }
}

// transpose Wv and Wo (tiny, one-shot)
__global__ void k_tr(const float* __restrict__ Wv, const float* __restrict__ Wo) {
    int i = blockIdx.x * blockDim.x + threadIdx.x;  // 0 .. 2*65536
    int which = i >> 16;
    int r = i & 0xFFFF;
    int j = r >> 8, c = r & 255;           // out index r = j*256 + c
    if (which == 0) g_WvT[r] = Wv[c * CC + j];
    else            g_WoT[r] = Wo[c * CC + j];
}

// scores[n][h] = x[n]·qw[h] + qc[h]; segment max (atomic); count histogram
__global__ void k_scores(const float* __restrict__ x, const int* __restrict__ poi, int N) {
    int lane = threadIdx.x & 31;
    int gw = (blockIdx.x * blockDim.x + threadIdx.x) >> 5;
    if (gw >= N) return;
    int n = gw;
    float4 q0[HH], q1[HH];
    #pragma unroll
    for (int h = 0; h < HH; h++) {
        q0[h] = *(const float4*)&g_qw[h * CC + lane * 4];
        q1[h] = *(const float4*)&g_qw[h * CC + 128 + lane * 4];
    }
    const float4* xr = (const float4*)(x + (size_t)n * CC);
    float4 x0 = xr[lane];
    float4 x1 = xr[32 + lane];
    float acc[HH];
    #pragma unroll
    for (int h = 0; h < HH; h++) {
        acc[h] = x0.x * q0[h].x + x0.y * q0[h].y + x0.z * q0[h].z + x0.w * q0[h].w
               + x1.x * q1[h].x + x1.y * q1[h].y + x1.z * q1[h].z + x1.w * q1[h].w;
    }
    #pragma unroll
    for (int off = 16; off > 0; off >>= 1) {
        #pragma unroll
        for (int h = 0; h < HH; h++)
            acc[h] += __shfl_xor_sync(0xffffffffu, acc[h], off);
    }
    if (lane == 0) {
        int p = poi[n];
        float a0 = acc[0] + g_qc[0], a1 = acc[1] + g_qc[1];
        float a2 = acc[2] + g_qc[2], a3 = acc[3] + g_qc[3];
        atomicMax(&g_smax[p * 4 + 0], encf(a0));
        atomicMax(&g_smax[p * 4 + 1], encf(a1));
        atomicMax(&g_smax[p * 4 + 2], encf(a2));
        atomicMax(&g_smax[p * 4 + 3], encf(a3));
        *(float4*)&g_scoreE[(size_t)n * 4] = make_float4(a0, a1, a2, a3);
        atomicAdd(&g_count[p], 1);
    }
}

// e = exp(score - smax[p]); denom = segment_sum(e)  (in-place score -> e)
__global__ void k_exp(const int* __restrict__ poi, int N) {
    int n = blockIdx.x * blockDim.x + threadIdx.x;
    if (n >= N) return;
    float4 s = *(const float4*)&g_scoreE[(size_t)n * 4];
    int p = poi[n];
    float e0 = expf(s.x - decf(g_smax[p * 4 + 0]));
    float e1 = expf(s.y - decf(g_smax[p * 4 + 1]));
    float e2 = expf(s.z - decf(g_smax[p * 4 + 2]));
    float e3 = expf(s.w - decf(g_smax[p * 4 + 3]));
    *(float4*)&g_scoreE[(size_t)n * 4] = make_float4(e0, e1, e2, e3);
    atomicAdd(&g_denom[p * 4 + 0], e0);
    atomicAdd(&g_denom[p * 4 + 1], e1);
    atomicAdd(&g_denom[p * 4 + 2], e2);
    atomicAdd(&g_denom[p * 4 + 3], e3);
}

// exclusive scan of counts -> offsets (single block, 1024 threads)
__global__ void k_scan(int N, int P) {
    __shared__ int s[1024];
    int t = threadIdx.x;
    int chunk = (P + 1023) / 1024;
    int beg = t * chunk, end = min(beg + chunk, P);
    int sum = 0;
    for (int i = beg; i < end; i++) sum += g_count[i];
    s[t] = sum;
    __syncthreads();
    for (int off = 1; off < 1024; off <<= 1) {
        int v = (t >= off) ? s[t - off] : 0;
        __syncthreads();
        s[t] += v;
        __syncthreads();
    }
    int run = s[t] - sum;          // exclusive prefix
    for (int i = beg; i < end; i++) { g_offsets[i] = run; run += g_count[i]; }
    if (t == 1023) g_offsets[P] = s[1023];
}

__global__ void k_scatter(const int* __restrict__ poi, int N) {
    int n = blockIdx.x * blockDim.x + threadIdx.x;
    if (n >= N) return;
    int p = poi[n];
    int pos = g_offsets[p] + atomicAdd(&g_fill[p], 1);
    g_order[pos] = n;
}

// xbar[p,h,:] = sum_{n in p} alpha[n,h] * x[n,:]   (warp per POI, atomic-free)
__global__ void k_gather(const float* __restrict__ x, int P) {
    int lane = threadIdx.x & 31;
    int p = (blockIdx.x * blockDim.x + threadIdx.x) >> 5;
    if (p >= P) return;
    int beg = g_offsets[p], end = g_offsets[p + 1];
    float rinv[HH];
    #pragma unroll
    for (int h = 0; h < HH; h++) rinv[h] = 1.0f / (g_denom[p * 4 + h] + 1e-16f);
    float a0[HH][4], a1[HH][4];
    #pragma unroll
    for (int h = 0; h < HH; h++)
        #pragma unroll
        for (int k = 0; k < 4; k++) { a0[h][k] = 0.f; a1[h][k] = 0.f; }
    for (int i = beg; i < end; i++) {
        int n = g_order[i];
        float4 e = *(const float4*)&g_scoreE[(size_t)n * 4];
        float al[HH] = { e.x * rinv[0], e.y * rinv[1], e.z * rinv[2], e.w * rinv[3] };
        const float4* xr = (const float4*)(x + (size_t)n * CC);
        float4 v0 = xr[lane];
        float4 v1 = xr[32 + lane];
        #pragma unroll
        for (int h = 0; h < HH; h++) {
            a0[h][0] += al[h] * v0.x; a0[h][1] += al[h] * v0.y;
            a0[h][2] += al[h] * v0.z; a0[h][3] += al[h] * v0.w;
            a1[h][0] += al[h] * v1.x; a1[h][1] += al[h] * v1.y;
            a1[h][2] += al[h] * v1.z; a1[h][3] += al[h] * v1.w;
        }
    }
    #pragma unroll
    for (int h = 0; h < HH; h++) {
        float* dst = &g_xbar[((size_t)p * HH + h) * CC];
        *(float4*)&dst[lane * 4]       = make_float4(a0[h][0], a0[h][1], a0[h][2], a0[h][3]);
        *(float4*)&dst[128 + lane * 4] = make_float4(a1[h][0], a1[h][1], a1[h][2], a1[h][3]);
    }
}

// Fused: O = Q + xbar@Wv^T(+bv*m); out = prelu(O + relu(O@Wo^T + bo))
__global__ void __launch_bounds__(256) k_fused(
    const float* __restrict__ bv, const float* __restrict__ bo,
    const float* __restrict__ prelu, float* __restrict__ out, int P)
{
    __shared__ float sO[TILE_P * CC];            // 32 KB
    __shared__ float sX[TILE_P * HH * 8];        // 4 KB  (j-chunk of xbar)
    __shared__ float sM[TILE_P * HH];
    int t = threadIdx.x;
    int c = t;                  // output channel, 0..255
    int h = c >> 6;
    int p0 = blockIdx.x * TILE_P;

    if (t < TILE_P * HH) {
        int pp = t >> 2, hh = t & 3;
        float d = (p0 + pp < P) ? g_denom[(p0 + pp) * 4 + hh] : 0.f;
        sM[t] = d / (d + 1e-16f);
    }

    unsigned long long acc2[TILE_P];
    #pragma unroll
    for (int pp = 0; pp < TILE_P; pp++) acc2[pp] = 0ull;

    // ---- Phase A: O tile = Q + xbar @ WvT + bv*m ----
    const unsigned long long* sX2 = (const unsigned long long*)sX;
    for (int j0 = 0; j0 < CC; j0 += 8) {
        // cooperative stage of xbar[p0..p0+31, :, j0..j0+7]
        {
            int pp = t >> 3, rem = t & 7;
            int hh = rem >> 1, half = rem & 1;
            float4 v = make_float4(0.f, 0.f, 0.f, 0.f);
            if (p0 + pp < P)
                v = *(const float4*)&g_xbar[(((size_t)(p0 + pp) * HH + hh) * CC) + j0 + half * 4];
            *(float4*)&sX[(pp * HH + hh) * 8 + half * 4] = v;
        }
        __syncthreads();
        float w[8];
        #pragma unroll
        for (int u = 0; u < 8; u++) w[u] = g_WvT[(j0 + u) * CC + c];
        unsigned long long w2[4];
        #pragma unroll
        for (int k = 0; k < 4; k++) w2[k] = pk2(w[2 * k], w[2 * k + 1]);
        #pragma unroll
        for (int pp = 0; pp < TILE_P; pp++) {
            int base = (pp * HH + h) * 4;     // ull index into sX
            fma2(acc2[pp], sX2[base + 0], w2[0]);
            fma2(acc2[pp], sX2[base + 1], w2[1]);
            fma2(acc2[pp], sX2[base + 2], w2[2]);
            fma2(acc2[pp], sX2[base + 3], w2[3]);
        }
        __syncthreads();
    }
    float qv = g_Q[c], bvc = bv[c];
    #pragma unroll
    for (int pp = 0; pp < TILE_P; pp++) {
        sO[pp * CC + c] = qv + hadd2(acc2[pp]) + bvc * sM[pp * HH + h];
        acc2[pp] = 0ull;
    }
    __syncthreads();

    // ---- Phase B: T = relu(O @ WoT + bo); out = prelu(O + T) ----
    const unsigned long long* sO2 = (const unsigned long long*)sO;
    for (int j0 = 0; j0 < CC; j0 += 8) {
        float w[8];
        #pragma unroll
        for (int u = 0; u < 8; u++) w[u] = g_WoT[(j0 + u) * CC + c];
        unsigned long long w2[4];
        #pragma unroll
        for (int k = 0; k < 4; k++) w2[k] = pk2(w[2 * k], w[2 * k + 1]);
        #pragma unroll
        for (int pp = 0; pp < TILE_P; pp++) {
            int base = pp * (CC / 2) + j0 / 2;
            fma2(acc2[pp], sO2[base + 0], w2[0]);
            fma2(acc2[pp], sO2[base + 1], w2[1]);
            fma2(acc2[pp], sO2[base + 2], w2[2]);
            fma2(acc2[pp], sO2[base + 3], w2[3]);
        }
    }
    float boc = bo[c], pa = prelu[0];
    #pragma unroll
    for (int pp = 0; pp < TILE_P; pp++) {
        if (p0 + pp < P) {
            float tt = fmaxf(hadd2(acc2[pp]) + boc, 0.f);
            float o = sO[pp * CC + c] + tt;
            o = (o >= 0.f) ? o : pa * o;
            out[(size_t)(p0 + pp) * CC + c] = o;
        }
    }
}

// ---------------- launch ----------------
extern "C" void kernel_launch(void* const* d_in, const int* in_sizes, int n_in,
                              void* d_out, int out_size) {
    // input order: x, checkin_to_poi, [num_pois], Wq, bq, Wk, bk, Wv, bv, Wo, bo, S, prelu_a
    int off = (n_in >= 13) ? 1 : 0;
    const float* x    = (const float*)d_in[0];
    const int*   poi  = (const int*)d_in[1];
    const float* Wq   = (const float*)d_in[2 + off];
    const float* bq   = (const float*)d_in[3 + off];
    const float* Wk   = (const float*)d_in[4 + off];
    const float* bk   = (const float*)d_in[5 + off];
    const float* Wv   = (const float*)d_in[6 + off];
    const float* bv   = (const float*)d_in[7 + off];
    const float* Wo   = (const float*)d_in[8 + off];
    const float* bo   = (const float*)d_in[9 + off];
    const float* S    = (const float*)d_in[10 + off];
    const float* pa   = (const float*)d_in[11 + off];
    float* out = (float*)d_out;

    int N = in_sizes[0] / CC;
    int P = out_size / CC;

    k_init<<<256, 256>>>(P);
    k_q<<<1, 256>>>(S, Wq, bq);
    k_qw<<<HH, 256>>>(Wk, bk);
    k_tr<<<512, 256>>>(Wv, Wo);
    k_scores<<<(N + 7) / 8, 256>>>(x, poi, N);
    k_exp<<<(N + 255) / 256, 256>>>(poi, N);
    k_scan<<<1, 1024>>>(N, P);
    k_scatter<<<(N + 255) / 256, 256>>>(poi, N);
    k_gather<<<(P + 7) / 8, 256>>>(x, P);
    k_fused<<<(P + TILE_P - 1) / TILE_P, 256>>>(bv, bo, pa, out, P);
}